// round 1
// baseline (speedup 1.0000x reference)
#include <cuda_runtime.h>
#include <cuda_bf16.h>

#define BB 2
#define LL 2048
#define DM 1024
#define NH 16
#define DK 64
#define MM (BB*LL)          // 4096 token rows
#define QT 64               // query tile
#define KT 64               // key tile
#define SROW 68             // padded smem row stride (floats, mult of 4)

// ---------------- scratch (device globals; no allocation allowed) ----------
__device__ float g_Q[BB*NH*LL*DK];      // [b][h][l][d]
__device__ float g_K[BB*NH*LL*DK];
__device__ float g_V[BB*NH*LL*DK];
__device__ float g_O[MM*DM];            // [b][l][D]  (attn @ V, normalized)
__device__ float g_inv[BB*NH*LL];       // 1/rowsum per (b,h,q)

// ============================================================================
// QKV projection: Q/K/V = x @ W^T + b, stored permuted as [b][h][l][d]
// Classic 128x128 tile, BK=8, 8x8 per thread, 256 threads.
// ============================================================================
__global__ __launch_bounds__(256) void qkv_proj_kernel(
    const float* __restrict__ x,
    const float* __restrict__ Wq, const float* __restrict__ Wk, const float* __restrict__ Wv,
    const float* __restrict__ bq, const float* __restrict__ bk, const float* __restrict__ bv)
{
    __shared__ float As[8][128];
    __shared__ float Bs[8][128];

    const int z = blockIdx.z;
    const float* W  = (z == 0) ? Wq : (z == 1 ? Wk : Wv);
    const float* bi = (z == 0) ? bq : (z == 1 ? bk : bv);
    float* dst      = (z == 0) ? g_Q : (z == 1 ? g_K : g_V);

    const int bm = blockIdx.y * 128;
    const int bn = blockIdx.x * 128;
    const int tid = threadIdx.x;
    const int tr = (tid >> 4) << 3;     // 0..120
    const int tc = (tid & 15) << 3;     // 0..120
    const int lr = tid >> 1;            // 0..127
    const int lk = (tid & 1) << 2;      // 0 or 4

    float acc[8][8];
    #pragma unroll
    for (int i = 0; i < 8; i++)
        #pragma unroll
        for (int j = 0; j < 8; j++) acc[i][j] = 0.f;

    for (int k0 = 0; k0 < DM; k0 += 8) {
        float4 av  = *(const float4*)(x + (size_t)(bm + lr) * DM + k0 + lk);
        float4 bv4 = *(const float4*)(W + (size_t)(bn + lr) * DM + k0 + lk);
        As[lk + 0][lr] = av.x;  As[lk + 1][lr] = av.y;
        As[lk + 2][lr] = av.z;  As[lk + 3][lr] = av.w;
        Bs[lk + 0][lr] = bv4.x; Bs[lk + 1][lr] = bv4.y;
        Bs[lk + 2][lr] = bv4.z; Bs[lk + 3][lr] = bv4.w;
        __syncthreads();
        #pragma unroll
        for (int k = 0; k < 8; k++) {
            float4 a0 = *(const float4*)(&As[k][tr]);
            float4 a1 = *(const float4*)(&As[k][tr + 4]);
            float4 b0 = *(const float4*)(&Bs[k][tc]);
            float4 b1 = *(const float4*)(&Bs[k][tc + 4]);
            float a[8] = {a0.x, a0.y, a0.z, a0.w, a1.x, a1.y, a1.z, a1.w};
            float b[8] = {b0.x, b0.y, b0.z, b0.w, b1.x, b1.y, b1.z, b1.w};
            #pragma unroll
            for (int i = 0; i < 8; i++)
                #pragma unroll
                for (int j = 0; j < 8; j++) acc[i][j] += a[i] * b[j];
        }
        __syncthreads();
    }

    #pragma unroll
    for (int i = 0; i < 8; i++) {
        int m = bm + tr + i;
        int bidx = m / LL;
        int l = m % LL;
        #pragma unroll
        for (int j = 0; j < 8; j++) {
            int o = bn + tc + j;
            int h = o >> 6;
            int d = o & 63;
            dst[(((size_t)bidx * NH + h) * LL + l) * DK + d] = acc[i][j] + bi[o];
        }
    }
}

// ============================================================================
// Fused attention block: per (b,h,qtile of 64): S = Q K^T / 8, e = exp(S)
// (masked -> 0), write unnormalized e to attn, accumulate rowsum and e@V,
// scale O by 1/rowsum, store O in [b][l][D] layout.
// 256 threads; 16x16 thread grid, 4x4 per thread over a 64x64 tile.
// ============================================================================
__global__ __launch_bounds__(256) void attn_kernel(
    const int* __restrict__ mask, float* __restrict__ attn_out)
{
    extern __shared__ char smem_raw[];
    float* Qs = (float*)smem_raw;                 // [d][q]  transposed, stride SROW
    float* Ks = Qs + 64 * SROW;                   // [d][k]  transposed
    float* Ps = Ks + 64 * SROW;                   // [q][k]  natural
    float* Vs = Ps + 64 * SROW;                   // [k][d]  natural
    int*   Ms = (int*)(Vs + 64 * SROW);           // [64]

    const int bh = blockIdx.y;                    // 0..31
    const int b  = bh >> 4;
    const int h  = bh & 15;
    const int q0 = blockIdx.x * QT;

    const float* Qb = g_Q + ((size_t)bh * LL + q0) * DK;
    const float* Kb = g_K + (size_t)bh * LL * DK;
    const float* Vb = g_V + (size_t)bh * LL * DK;

    const int tid = threadIdx.x;
    const int tq  = tid >> 4;     // 0..15
    const int tk  = tid & 15;     // 0..15

    // load Q tile transposed
    #pragma unroll
    for (int i = 0; i < 4; i++) {
        int idx = tid + i * 256;
        int q   = idx >> 4;
        int dg  = (idx & 15) << 2;
        float4 v = *(const float4*)(Qb + q * DK + dg);
        Qs[(dg + 0) * SROW + q] = v.x;
        Qs[(dg + 1) * SROW + q] = v.y;
        Qs[(dg + 2) * SROW + q] = v.z;
        Qs[(dg + 3) * SROW + q] = v.w;
    }

    float o[4][4];
    #pragma unroll
    for (int i = 0; i < 4; i++)
        #pragma unroll
        for (int j = 0; j < 4; j++) o[i][j] = 0.f;
    float rs[4] = {0.f, 0.f, 0.f, 0.f};

    for (int kt = 0; kt < LL / KT; kt++) {
        const float* Kt = Kb + kt * KT * DK;
        const float* Vt = Vb + kt * KT * DK;
        #pragma unroll
        for (int i = 0; i < 4; i++) {
            int idx = tid + i * 256;
            int r   = idx >> 4;
            int dg  = (idx & 15) << 2;
            float4 kv = *(const float4*)(Kt + r * DK + dg);
            Ks[(dg + 0) * SROW + r] = kv.x;
            Ks[(dg + 1) * SROW + r] = kv.y;
            Ks[(dg + 2) * SROW + r] = kv.z;
            Ks[(dg + 3) * SROW + r] = kv.w;
            *(float4*)(Vs + r * SROW + dg) = *(const float4*)(Vt + r * DK + dg);
        }
        if (tid < 64) Ms[tid] = mask[b * LL + kt * KT + tid];
        __syncthreads();

        // S = Q K^T
        float s[4][4];
        #pragma unroll
        for (int i = 0; i < 4; i++)
            #pragma unroll
            for (int j = 0; j < 4; j++) s[i][j] = 0.f;
        #pragma unroll
        for (int d = 0; d < 64; d++) {
            float4 a = *(const float4*)(Qs + d * SROW + (tq << 2));
            float4 k4 = *(const float4*)(Ks + d * SROW + (tk << 2));
            s[0][0] += a.x * k4.x; s[0][1] += a.x * k4.y; s[0][2] += a.x * k4.z; s[0][3] += a.x * k4.w;
            s[1][0] += a.y * k4.x; s[1][1] += a.y * k4.y; s[1][2] += a.y * k4.z; s[1][3] += a.y * k4.w;
            s[2][0] += a.z * k4.x; s[2][1] += a.z * k4.y; s[2][2] += a.z * k4.z; s[2][3] += a.z * k4.w;
            s[3][0] += a.w * k4.x; s[3][1] += a.w * k4.y; s[3][2] += a.w * k4.z; s[3][3] += a.w * k4.w;
        }

        // e = exp(s/8) with mask; rowsum; stash to Ps; emit unnormalized attn
        int mj[4];
        #pragma unroll
        for (int j = 0; j < 4; j++) mj[j] = Ms[(tk << 2) + j];
        #pragma unroll
        for (int i = 0; i < 4; i++) {
            #pragma unroll
            for (int j = 0; j < 4; j++) {
                float e = mj[j] ? __expf(s[i][j] * 0.125f) : 0.f;
                s[i][j] = e;
                rs[i] += e;
            }
            *(float4*)(Ps + ((tq << 2) + i) * SROW + (tk << 2)) =
                make_float4(s[i][0], s[i][1], s[i][2], s[i][3]);
            if (attn_out) {
                size_t row = (size_t)bh * LL + q0 + (tq << 2) + i;
                *(float4*)(attn_out + row * LL + kt * KT + (tk << 2)) =
                    make_float4(s[i][0], s[i][1], s[i][2], s[i][3]);
            }
        }
        __syncthreads();

        // O += P @ V
        #pragma unroll
        for (int kk = 0; kk < 64; kk++) {
            float4 v = *(const float4*)(Vs + kk * SROW + (tk << 2));
            float p0 = Ps[((tq << 2) + 0) * SROW + kk];
            float p1 = Ps[((tq << 2) + 1) * SROW + kk];
            float p2 = Ps[((tq << 2) + 2) * SROW + kk];
            float p3 = Ps[((tq << 2) + 3) * SROW + kk];
            o[0][0] += p0 * v.x; o[0][1] += p0 * v.y; o[0][2] += p0 * v.z; o[0][3] += p0 * v.w;
            o[1][0] += p1 * v.x; o[1][1] += p1 * v.y; o[1][2] += p1 * v.z; o[1][3] += p1 * v.w;
            o[2][0] += p2 * v.x; o[2][1] += p2 * v.y; o[2][2] += p2 * v.z; o[2][3] += p2 * v.w;
            o[3][0] += p3 * v.x; o[3][1] += p3 * v.y; o[3][2] += p3 * v.z; o[3][3] += p3 * v.w;
        }
        __syncthreads();
    }

    // rowsum reduce across the 16 tk lanes (they sit in one 16-lane half-warp)
    #pragma unroll
    for (int off = 8; off > 0; off >>= 1) {
        #pragma unroll
        for (int i = 0; i < 4; i++)
            rs[i] += __shfl_xor_sync(0xffffffffu, rs[i], off);
    }
    float inv[4];
    #pragma unroll
    for (int i = 0; i < 4; i++) inv[i] = 1.f / rs[i];
    if (tk == 0) {
        #pragma unroll
        for (int i = 0; i < 4; i++)
            g_inv[(size_t)bh * LL + q0 + (tq << 2) + i] = inv[i];
    }

    // store normalized O in [b][l][D] layout
    #pragma unroll
    for (int i = 0; i < 4; i++) {
        int q = q0 + (tq << 2) + i;
        *(float4*)(g_O + ((size_t)b * LL + q) * DM + h * DK + (tk << 2)) =
            make_float4(o[i][0] * inv[i], o[i][1] * inv[i],
                        o[i][2] * inv[i], o[i][3] * inv[i]);
    }
}

// ============================================================================
// normalize attn: attn[row][k] *= 1/rowsum[row]
// ============================================================================
__global__ __launch_bounds__(256) void norm_attn_kernel(float4* __restrict__ attn)
{
    int i4 = blockIdx.x * 256 + threadIdx.x;      // 0 .. 33554431
    int row = i4 >> 9;                            // (i4*4)/2048
    float inv = g_inv[row];
    float4 v = attn[i4];
    v.x *= inv; v.y *= inv; v.z *= inv; v.w *= inv;
    attn[i4] = v;
}

// ============================================================================
// output projection: out = O @ Wo^T + bo  (plain store)
// ============================================================================
__global__ __launch_bounds__(256) void out_proj_kernel(
    const float* __restrict__ Wo, const float* __restrict__ bo,
    float* __restrict__ out)
{
    __shared__ float As[8][128];
    __shared__ float Bs[8][128];

    const int bm = blockIdx.y * 128;
    const int bn = blockIdx.x * 128;
    const int tid = threadIdx.x;
    const int tr = (tid >> 4) << 3;
    const int tc = (tid & 15) << 3;
    const int lr = tid >> 1;
    const int lk = (tid & 1) << 2;

    float acc[8][8];
    #pragma unroll
    for (int i = 0; i < 8; i++)
        #pragma unroll
        for (int j = 0; j < 8; j++) acc[i][j] = 0.f;

    for (int k0 = 0; k0 < DM; k0 += 8) {
        float4 av  = *(const float4*)(g_O + (size_t)(bm + lr) * DM + k0 + lk);
        float4 bv4 = *(const float4*)(Wo  + (size_t)(bn + lr) * DM + k0 + lk);
        As[lk + 0][lr] = av.x;  As[lk + 1][lr] = av.y;
        As[lk + 2][lr] = av.z;  As[lk + 3][lr] = av.w;
        Bs[lk + 0][lr] = bv4.x; Bs[lk + 1][lr] = bv4.y;
        Bs[lk + 2][lr] = bv4.z; Bs[lk + 3][lr] = bv4.w;
        __syncthreads();
        #pragma unroll
        for (int k = 0; k < 8; k++) {
            float4 a0 = *(const float4*)(&As[k][tr]);
            float4 a1 = *(const float4*)(&As[k][tr + 4]);
            float4 b0 = *(const float4*)(&Bs[k][tc]);
            float4 b1 = *(const float4*)(&Bs[k][tc + 4]);
            float a[8] = {a0.x, a0.y, a0.z, a0.w, a1.x, a1.y, a1.z, a1.w};
            float b[8] = {b0.x, b0.y, b0.z, b0.w, b1.x, b1.y, b1.z, b1.w};
            #pragma unroll
            for (int i = 0; i < 8; i++)
                #pragma unroll
                for (int j = 0; j < 8; j++) acc[i][j] += a[i] * b[j];
        }
        __syncthreads();
    }

    #pragma unroll
    for (int i = 0; i < 8; i++) {
        int m = bm + tr + i;
        #pragma unroll
        for (int j = 0; j < 8; j++) {
            int o = bn + tc + j;
            out[(size_t)m * DM + o] = acc[i][j] + bo[o];
        }
    }
}

// ============================================================================
extern "C" void kernel_launch(void* const* d_in, const int* in_sizes, int n_in,
                              void* d_out, int out_size)
{
    const float* x    = (const float*)d_in[0];
    const int*   mask = (const int*)  d_in[1];
    const float* Wq   = (const float*)d_in[2];
    const float* bq   = (const float*)d_in[3];
    const float* Wk   = (const float*)d_in[4];
    const float* bk   = (const float*)d_in[5];
    const float* Wv   = (const float*)d_in[6];
    const float* bv   = (const float*)d_in[7];
    const float* Wo   = (const float*)d_in[8];
    const float* bo   = (const float*)d_in[9];
    float* out = (float*)d_out;

    const size_t out_elems  = (size_t)BB * LL * DM;            // 4,194,304
    const size_t attn_elems = (size_t)BB * NH * LL * LL;       // 134,217,728
    float* attn = ((size_t)out_size >= out_elems + attn_elems)
                      ? (out + out_elems) : nullptr;

    const int smem_attn = (4 * 64 * SROW) * (int)sizeof(float) + 64 * (int)sizeof(int);
    cudaFuncSetAttribute(attn_kernel,
                         cudaFuncAttributeMaxDynamicSharedMemorySize, smem_attn);

    qkv_proj_kernel<<<dim3(DM / 128, MM / 128, 3), 256>>>(x, Wq, Wk, Wv, bq, bk, bv);
    attn_kernel<<<dim3(LL / QT, BB * NH), 256, smem_attn>>>(mask, attn);
    if (attn) {
        norm_attn_kernel<<<(int)(attn_elems / 4 / 256), 256>>>((float4*)attn);
    }
    out_proj_kernel<<<dim3(DM / 128, MM / 128), 256>>>(Wo, bo, out);
}